// round 1
// baseline (speedup 1.0000x reference)
#include <cuda_runtime.h>
#include <cstdint>

// ---------------------------------------------------------------------------
// Problem constants
// ---------------------------------------------------------------------------
#define B_DIM 8
#define L_DIM 1024
#define D_MODEL 1024
#define N_HEADS 16
#define D_KEYS 64
#define D_LLM 4096
#define HD 1024           // N_HEADS * D_KEYS
#define ML (B_DIM * L_DIM) // 8192 rows of q / attn output

// Scratch (device globals: allocation-free contract)
__device__ float g_q[ML * HD];        // 32 MB
__device__ float g_k[1024 * HD];      // 4 MB (S<=1024)
__device__ float g_v[1024 * HD];      // 4 MB
__device__ float g_attn[ML * HD];     // 32 MB

// ---------------------------------------------------------------------------
// SGEMM: C[M,N] = A[M,K] @ W[K,N] + bias[N]
// 128x128 tile, BK=8, 256 threads, 8x8 per-thread microtile, smem ping-pong.
// Requirements: K % 8 == 0, N % 128 == 0. M may be ragged (guarded).
// ---------------------------------------------------------------------------
#define BM 128
#define BN 128
#define BK 8

__global__ __launch_bounds__(256, 2)
void sgemm_bias_kernel(const float* __restrict__ A, const float* __restrict__ W,
                       const float* __restrict__ bias, float* __restrict__ C,
                       int M, int N, int K)
{
    __shared__ float As[2][BK][BM];
    __shared__ float Bs[2][BK][BN];

    const int tid = threadIdx.x;
    const int m0 = blockIdx.y * BM;
    const int n0 = blockIdx.x * BN;

    // A-tile loader mapping: each thread loads one float4 along K
    const int a_i = tid >> 1;            // 0..127 (row within tile)
    const int a_k = (tid & 1) << 2;      // 0 or 4
    // B-tile loader mapping: each thread loads one float4 along N
    const int b_k = tid >> 5;            // 0..7
    const int b_j = (tid & 31) << 2;     // 0..124

    const int tx = tid & 15;             // col group (8 cols)
    const int ty = tid >> 4;             // row group (8 rows)

    const int nk = K / BK;

    float acc[8][8];
    #pragma unroll
    for (int u = 0; u < 8; u++)
        #pragma unroll
        for (int v = 0; v < 8; v++) acc[u][v] = 0.0f;

    float4 aR, bR;
    // ---- prologue: tile 0 ----
    {
        const int row = m0 + a_i;
        aR = (row < M) ? *(const float4*)(A + (size_t)row * K + a_k)
                       : make_float4(0.f, 0.f, 0.f, 0.f);
        bR = *(const float4*)(W + (size_t)b_k * N + n0 + b_j);
    }
    As[0][a_k + 0][a_i] = aR.x;
    As[0][a_k + 1][a_i] = aR.y;
    As[0][a_k + 2][a_i] = aR.z;
    As[0][a_k + 3][a_i] = aR.w;
    *(float4*)&Bs[0][b_k][b_j] = bR;
    __syncthreads();

    for (int kt = 0; kt < nk; kt++) {
        const int cur = kt & 1;
        if (kt + 1 < nk) {
            const int k0 = (kt + 1) * BK;
            const int row = m0 + a_i;
            aR = (row < M) ? *(const float4*)(A + (size_t)row * K + k0 + a_k)
                           : make_float4(0.f, 0.f, 0.f, 0.f);
            bR = *(const float4*)(W + (size_t)(k0 + b_k) * N + n0 + b_j);
        }

        #pragma unroll
        for (int kk = 0; kk < BK; kk++) {
            float a[8], b[8];
            *(float4*)(a)     = *(const float4*)&As[cur][kk][ty * 8];
            *(float4*)(a + 4) = *(const float4*)&As[cur][kk][ty * 8 + 4];
            *(float4*)(b)     = *(const float4*)&Bs[cur][kk][tx * 8];
            *(float4*)(b + 4) = *(const float4*)&Bs[cur][kk][tx * 8 + 4];
            #pragma unroll
            for (int u = 0; u < 8; u++)
                #pragma unroll
                for (int v = 0; v < 8; v++)
                    acc[u][v] = fmaf(a[u], b[v], acc[u][v]);
        }

        if (kt + 1 < nk) {
            const int nxt = cur ^ 1;
            As[nxt][a_k + 0][a_i] = aR.x;
            As[nxt][a_k + 1][a_i] = aR.y;
            As[nxt][a_k + 2][a_i] = aR.z;
            As[nxt][a_k + 3][a_i] = aR.w;
            *(float4*)&Bs[nxt][b_k][b_j] = bR;
            __syncthreads();
        }
    }

    // ---- epilogue ----
    float bv0[8];
    *(float4*)(bv0)     = *(const float4*)(bias + n0 + tx * 8);
    *(float4*)(bv0 + 4) = *(const float4*)(bias + n0 + tx * 8 + 4);

    #pragma unroll
    for (int u = 0; u < 8; u++) {
        const int row = m0 + ty * 8 + u;
        if (row < M) {
            float4 o0 = make_float4(acc[u][0] + bv0[0], acc[u][1] + bv0[1],
                                    acc[u][2] + bv0[2], acc[u][3] + bv0[3]);
            float4 o1 = make_float4(acc[u][4] + bv0[4], acc[u][5] + bv0[5],
                                    acc[u][6] + bv0[6], acc[u][7] + bv0[7]);
            *(float4*)(C + (size_t)row * N + n0 + tx * 8)     = o0;
            *(float4*)(C + (size_t)row * N + n0 + tx * 8 + 4) = o1;
        }
    }
}

// ---------------------------------------------------------------------------
// Fused cross-attention (flash-style, no mask, head_dim = 64).
// One block per (b, h, 64-query tile). 256 threads, 4x4 microtiles.
//   scores = scale * (q . k), online softmax over S, O += P @ V.
// K smem buffer is reused for P (scores GEMM finishes before P is written).
// ---------------------------------------------------------------------------
#define AT_PAD 65

__global__ __launch_bounds__(256)
void attn_kernel(const float* __restrict__ q, const float* __restrict__ k,
                 const float* __restrict__ v, float* __restrict__ o_out,
                 const float* __restrict__ alpha, const float* __restrict__ beta,
                 int S)
{
    extern __shared__ float sm[];
    float* Qs  = sm;                    // [e][i]  64 x 65
    float* KPs = sm + 64 * AT_PAD;      // K: [e][j]; later P: [s][i]
    float* Vs  = sm + 2 * 64 * AT_PAD;  // [s][d]  64 x 65

    const int tid = threadIdx.x;
    const int l0 = blockIdx.x * 64;
    const int b  = blockIdx.y >> 4;
    const int h  = blockIdx.y & 15;

    const int tr = tid >> 4;   // 0..15 -> query rows 4*tr..4*tr+3
    const int tc = tid & 15;   // 0..15 -> cols 4*tc..4*tc+3

    const float scale = alpha[0] * beta[0] * 0.125f;   // 1/sqrt(64)

    // load Q tile transposed: Qs[e][i] = q[b, l0+i, h*64+e]
    {
        const float* qbase = q + ((size_t)(b * L_DIM + l0)) * HD + h * D_KEYS;
        #pragma unroll
        for (int t = 0; t < 16; t++) {
            const int idx = t * 256 + tid;
            const int i = idx >> 6;
            const int e = idx & 63;
            Qs[e * AT_PAD + i] = qbase[(size_t)i * HD + e];
        }
    }

    float m_r[4], l_r[4], o_r[4][4];
    #pragma unroll
    for (int u = 0; u < 4; u++) {
        m_r[u] = -1e30f;
        l_r[u] = 0.0f;
        #pragma unroll
        for (int w = 0; w < 4; w++) o_r[u][w] = 0.0f;
    }

    const int nTiles = (S + 63) >> 6;
    for (int ts = 0; ts < nTiles; ts++) {
        const int s0 = ts * 64;
        __syncthreads();   // previous iteration done reading KPs/Vs (+ Q visible)

        // load K transposed [e][j] and V natural [j][e]
        const float* kbase = k + (size_t)s0 * HD + h * D_KEYS;
        const float* vbase = v + (size_t)s0 * HD + h * D_KEYS;
        #pragma unroll
        for (int t = 0; t < 16; t++) {
            const int idx = t * 256 + tid;
            const int j = idx >> 6;
            const int e = idx & 63;
            const bool valid = (s0 + j) < S;
            KPs[e * AT_PAD + j] = valid ? kbase[(size_t)j * HD + e] : 0.0f;
            Vs[j * AT_PAD + e]  = valid ? vbase[(size_t)j * HD + e] : 0.0f;
        }
        __syncthreads();

        // scores: sv[u][w] = sum_e Qs[e][4tr+u] * KPs[e][4tc+w]
        float sv[4][4];
        #pragma unroll
        for (int u = 0; u < 4; u++)
            #pragma unroll
            for (int w = 0; w < 4; w++) sv[u][w] = 0.0f;

        #pragma unroll 8
        for (int e = 0; e < 64; e++) {
            float qa[4], kb[4];
            #pragma unroll
            for (int u = 0; u < 4; u++) qa[u] = Qs[e * AT_PAD + 4 * tr + u];
            #pragma unroll
            for (int w = 0; w < 4; w++) kb[w] = KPs[e * AT_PAD + 4 * tc + w];
            #pragma unroll
            for (int u = 0; u < 4; u++)
                #pragma unroll
                for (int w = 0; w < 4; w++)
                    sv[u][w] = fmaf(qa[u], kb[w], sv[u][w]);
        }

        // scale + mask out-of-range s columns
        #pragma unroll
        for (int w = 0; w < 4; w++) {
            const bool valid = (s0 + 4 * tc + w) < S;
            #pragma unroll
            for (int u = 0; u < 4; u++)
                sv[u][w] = valid ? sv[u][w] * scale : -1e30f;
        }

        // online softmax update
        #pragma unroll
        for (int u = 0; u < 4; u++) {
            float mt = sv[u][0];
            mt = fmaxf(mt, sv[u][1]);
            mt = fmaxf(mt, sv[u][2]);
            mt = fmaxf(mt, sv[u][3]);
            #pragma unroll
            for (int off = 8; off >= 1; off >>= 1)
                mt = fmaxf(mt, __shfl_xor_sync(0xffffffffu, mt, off));
            const float m_new = fmaxf(m_r[u], mt);
            const float fac = __expf(m_r[u] - m_new);
            m_r[u] = m_new;
            l_r[u] *= fac;
            #pragma unroll
            for (int w = 0; w < 4; w++) o_r[u][w] *= fac;

            float rs = 0.0f;
            #pragma unroll
            for (int w = 0; w < 4; w++) {
                const float p = __expf(sv[u][w] - m_new);
                sv[u][w] = p;
                rs += p;
            }
            #pragma unroll
            for (int off = 8; off >= 1; off >>= 1)
                rs += __shfl_xor_sync(0xffffffffu, rs, off);
            l_r[u] += rs;
        }

        __syncthreads();   // everyone done reading K from KPs

        // store P transposed: KPs[s][i] = p
        #pragma unroll
        for (int w = 0; w < 4; w++)
            #pragma unroll
            for (int u = 0; u < 4; u++)
                KPs[(4 * tc + w) * AT_PAD + 4 * tr + u] = sv[u][w];
        __syncthreads();

        // O += P @ V
        #pragma unroll 8
        for (int s = 0; s < 64; s++) {
            float pa[4], vb[4];
            #pragma unroll
            for (int u = 0; u < 4; u++) pa[u] = KPs[s * AT_PAD + 4 * tr + u];
            #pragma unroll
            for (int w = 0; w < 4; w++) vb[w] = Vs[s * AT_PAD + 4 * tc + w];
            #pragma unroll
            for (int u = 0; u < 4; u++)
                #pragma unroll
                for (int w = 0; w < 4; w++)
                    o_r[u][w] = fmaf(pa[u], vb[w], o_r[u][w]);
        }
    }

    // normalize and write out: attn[b, l0+i, h*64+d]
    float* obase = o_out + ((size_t)(b * L_DIM + l0)) * HD + h * D_KEYS;
    #pragma unroll
    for (int u = 0; u < 4; u++) {
        const float inv = 1.0f / l_r[u];
        #pragma unroll
        for (int w = 0; w < 4; w++)
            obase[(size_t)(4 * tr + u) * HD + 4 * tc + w] = o_r[u][w] * inv;
    }
}

// ---------------------------------------------------------------------------
// Launch
// ---------------------------------------------------------------------------
extern "C" void kernel_launch(void* const* d_in, const int* in_sizes, int n_in,
                              void* d_out, int out_size)
{
    const float* target = (const float*)d_in[0];
    const float* source = (const float*)d_in[1];
    const float* value  = (const float*)d_in[2];
    const float* Wq = (const float*)d_in[3];
    const float* bq = (const float*)d_in[4];
    const float* Wk = (const float*)d_in[5];
    const float* bk = (const float*)d_in[6];
    const float* Wv = (const float*)d_in[7];
    const float* bv = (const float*)d_in[8];
    const float* Wo = (const float*)d_in[9];
    const float* bo = (const float*)d_in[10];
    const float* alpha = (const float*)d_in[11];
    const float* beta  = (const float*)d_in[12];
    float* out = (float*)d_out;

    const int S = in_sizes[1] / D_LLM;   // 1000

    float *qb, *kb, *vb, *ab;
    cudaGetSymbolAddress((void**)&qb, g_q);
    cudaGetSymbolAddress((void**)&kb, g_k);
    cudaGetSymbolAddress((void**)&vb, g_v);
    cudaGetSymbolAddress((void**)&ab, g_attn);

    dim3 blk(256);

    // Q = target @ Wq + bq          [8192,1024] x [1024,1024]
    sgemm_bias_kernel<<<dim3(HD / BN, ML / BM), blk>>>(target, Wq, bq, qb, ML, HD, D_MODEL);
    // K = source @ Wk + bk          [S,4096] x [4096,1024]
    sgemm_bias_kernel<<<dim3(HD / BN, (S + BM - 1) / BM), blk>>>(source, Wk, bk, kb, S, HD, D_LLM);
    // V = value @ Wv + bv
    sgemm_bias_kernel<<<dim3(HD / BN, (S + BM - 1) / BM), blk>>>(value, Wv, bv, vb, S, HD, D_LLM);

    // fused attention
    const size_t smem = 3 * 64 * AT_PAD * sizeof(float);   // ~49.9 KB
    cudaFuncSetAttribute(attn_kernel, cudaFuncAttributeMaxDynamicSharedMemorySize, (int)smem);
    attn_kernel<<<dim3(L_DIM / 64, B_DIM * N_HEADS), blk, smem>>>(qb, kb, vb, ab, alpha, beta, S);

    // out = attn @ Wo + bo          [8192,1024] x [1024,4096]
    sgemm_bias_kernel<<<dim3(D_LLM / BN, ML / BM), blk>>>(ab, Wo, bo, out, ML, D_LLM, D_MODEL);
}

// round 2
// speedup vs baseline: 1.8031x; 1.8031x over previous
#include <cuda_runtime.h>
#include <cstdint>

// ---------------------------------------------------------------------------
// Problem constants
// ---------------------------------------------------------------------------
#define B_DIM 8
#define L_DIM 1024
#define D_MODEL 1024
#define N_HEADS 16
#define D_KEYS 64
#define D_LLM 4096
#define HD 1024           // N_HEADS * D_KEYS
#define ML (B_DIM * L_DIM) // 8192 rows of q / attn output

// Scratch (device globals: allocation-free contract)
__device__ float g_q[ML * HD];        // 32 MB
__device__ float g_k[1024 * HD];      // 4 MB (S<=1024)
__device__ float g_v[1024 * HD];      // 4 MB
__device__ float g_attn[ML * HD];     // 32 MB

// ---------------------------------------------------------------------------
// TF32 tensor-core GEMM: C[M,N] = A[M,K] @ W[K,N] + bias[N]
// 128x128 CTA tile, BK=8, 256 threads (8 warps, 2x4), warp tile 64x32,
// mma.sync.m16n8k8.tf32. fp32 -> tf32 (rna) conversion on smem store.
// Requirements: K % 8 == 0, N % 128 == 0. M may be ragged (guarded).
// ---------------------------------------------------------------------------
#define BMT 128
#define BNT 128
#define BKT 8
#define APITCH 12     // bank-distinct for A frag reads (m=lane/4, k=lane%4[+4])
#define BPITCH 136    // bank-distinct for B frag reads (k=lane%4[+4], n=lane/4)

__device__ __forceinline__ uint32_t f32_to_tf32(float x) {
    uint32_t r;
    asm("cvt.rna.tf32.f32 %0, %1;" : "=r"(r) : "f"(x));
    return r;
}

__global__ __launch_bounds__(256, 2)
void gemm_tf32_kernel(const float* __restrict__ A, const float* __restrict__ W,
                      const float* __restrict__ bias, float* __restrict__ C,
                      int M, int N, int K)
{
    __shared__ uint32_t As[2][BMT][APITCH];
    __shared__ uint32_t Bs[2][BKT][BPITCH];

    const int tid  = threadIdx.x;
    const int lane = tid & 31;
    const int warp = tid >> 5;
    const int wm = (warp >> 2) * 64;   // warp M offset (0 or 64)
    const int wn = (warp & 3) * 32;    // warp N offset (0,32,64,96)
    const int grp = lane >> 2;         // 0..7
    const int tig = lane & 3;          // 0..3

    const int m0 = blockIdx.y * BMT;
    const int n0 = blockIdx.x * BNT;

    // loaders: one float4 per thread per tile
    const int la_row = tid >> 1;            // 0..127
    const int la_k   = (tid & 1) << 2;      // 0 or 4
    const int lb_k   = tid >> 5;            // 0..7
    const int lb_n   = (tid & 31) << 2;     // 0..124

    float acc[4][4][4];
    #pragma unroll
    for (int i = 0; i < 4; i++)
        #pragma unroll
        for (int j = 0; j < 4; j++)
            #pragma unroll
            for (int r = 0; r < 4; r++) acc[i][j][r] = 0.0f;

    const int nk = K / BKT;

    float4 aR, bR;
    // ---- prologue: tile 0 ----
    {
        const int row = m0 + la_row;
        aR = (row < M) ? *(const float4*)(A + (size_t)row * K + la_k)
                       : make_float4(0.f, 0.f, 0.f, 0.f);
        bR = *(const float4*)(W + (size_t)lb_k * N + n0 + lb_n);
    }
    As[0][la_row][la_k + 0] = f32_to_tf32(aR.x);
    As[0][la_row][la_k + 1] = f32_to_tf32(aR.y);
    As[0][la_row][la_k + 2] = f32_to_tf32(aR.z);
    As[0][la_row][la_k + 3] = f32_to_tf32(aR.w);
    Bs[0][lb_k][lb_n + 0] = f32_to_tf32(bR.x);
    Bs[0][lb_k][lb_n + 1] = f32_to_tf32(bR.y);
    Bs[0][lb_k][lb_n + 2] = f32_to_tf32(bR.z);
    Bs[0][lb_k][lb_n + 3] = f32_to_tf32(bR.w);
    __syncthreads();

    for (int kt = 0; kt < nk; kt++) {
        const int cur = kt & 1;
        if (kt + 1 < nk) {
            const int k0 = (kt + 1) * BKT;
            const int row = m0 + la_row;
            aR = (row < M) ? *(const float4*)(A + (size_t)row * K + k0 + la_k)
                           : make_float4(0.f, 0.f, 0.f, 0.f);
            bR = *(const float4*)(W + (size_t)(k0 + lb_k) * N + n0 + lb_n);
        }

        // fragments
        uint32_t af[4][4], bf[4][2];
        #pragma unroll
        for (int tm = 0; tm < 4; tm++) {
            const int rb = wm + tm * 16 + grp;
            af[tm][0] = As[cur][rb][tig];
            af[tm][1] = As[cur][rb + 8][tig];
            af[tm][2] = As[cur][rb][tig + 4];
            af[tm][3] = As[cur][rb + 8][tig + 4];
        }
        #pragma unroll
        for (int tn = 0; tn < 4; tn++) {
            const int nb = wn + tn * 8 + grp;
            bf[tn][0] = Bs[cur][tig][nb];
            bf[tn][1] = Bs[cur][tig + 4][nb];
        }

        #pragma unroll
        for (int tm = 0; tm < 4; tm++)
            #pragma unroll
            for (int tn = 0; tn < 4; tn++) {
                asm volatile(
                    "mma.sync.aligned.m16n8k8.row.col.f32.tf32.tf32.f32 "
                    "{%0,%1,%2,%3}, {%4,%5,%6,%7}, {%8,%9}, {%0,%1,%2,%3};"
                    : "+f"(acc[tm][tn][0]), "+f"(acc[tm][tn][1]),
                      "+f"(acc[tm][tn][2]), "+f"(acc[tm][tn][3])
                    : "r"(af[tm][0]), "r"(af[tm][1]), "r"(af[tm][2]), "r"(af[tm][3]),
                      "r"(bf[tn][0]), "r"(bf[tn][1]));
            }

        if (kt + 1 < nk) {
            const int nxt = cur ^ 1;
            As[nxt][la_row][la_k + 0] = f32_to_tf32(aR.x);
            As[nxt][la_row][la_k + 1] = f32_to_tf32(aR.y);
            As[nxt][la_row][la_k + 2] = f32_to_tf32(aR.z);
            As[nxt][la_row][la_k + 3] = f32_to_tf32(aR.w);
            Bs[nxt][lb_k][lb_n + 0] = f32_to_tf32(bR.x);
            Bs[nxt][lb_k][lb_n + 1] = f32_to_tf32(bR.y);
            Bs[nxt][lb_k][lb_n + 2] = f32_to_tf32(bR.z);
            Bs[nxt][lb_k][lb_n + 3] = f32_to_tf32(bR.w);
            __syncthreads();
        }
    }

    // ---- epilogue: bias + store ----
    #pragma unroll
    for (int tm = 0; tm < 4; tm++) {
        const int row  = m0 + wm + tm * 16 + grp;
        const int row2 = row + 8;
        #pragma unroll
        for (int tn = 0; tn < 4; tn++) {
            const int col = n0 + wn + tn * 8 + 2 * tig;
            const float b0v = bias[col];
            const float b1v = bias[col + 1];
            if (row < M) {
                float2 o = make_float2(acc[tm][tn][0] + b0v, acc[tm][tn][1] + b1v);
                *(float2*)(C + (size_t)row * N + col) = o;
            }
            if (row2 < M) {
                float2 o = make_float2(acc[tm][tn][2] + b0v, acc[tm][tn][3] + b1v);
                *(float2*)(C + (size_t)row2 * N + col) = o;
            }
        }
    }
}

// ---------------------------------------------------------------------------
// Fused cross-attention (flash-style, no mask, head_dim = 64).
// One block per (b, h, 64-query tile). 256 threads, 4x4 microtiles.
// ---------------------------------------------------------------------------
#define AT_PAD 65

__global__ __launch_bounds__(256)
void attn_kernel(const float* __restrict__ q, const float* __restrict__ k,
                 const float* __restrict__ v, float* __restrict__ o_out,
                 const float* __restrict__ alpha, const float* __restrict__ beta,
                 int S)
{
    extern __shared__ float sm[];
    float* Qs  = sm;                    // [e][i]  64 x 65
    float* KPs = sm + 64 * AT_PAD;      // K: [e][j]; later P: [s][i]
    float* Vs  = sm + 2 * 64 * AT_PAD;  // [s][d]  64 x 65

    const int tid = threadIdx.x;
    const int l0 = blockIdx.x * 64;
    const int b  = blockIdx.y >> 4;
    const int h  = blockIdx.y & 15;

    const int tr = tid >> 4;   // 0..15 -> query rows 4*tr..4*tr+3
    const int tc = tid & 15;   // 0..15 -> cols 4*tc..4*tc+3

    const float scale = alpha[0] * beta[0] * 0.125f;   // 1/sqrt(64)

    // load Q tile transposed: Qs[e][i] = q[b, l0+i, h*64+e]
    {
        const float* qbase = q + ((size_t)(b * L_DIM + l0)) * HD + h * D_KEYS;
        #pragma unroll
        for (int t = 0; t < 16; t++) {
            const int idx = t * 256 + tid;
            const int i = idx >> 6;
            const int e = idx & 63;
            Qs[e * AT_PAD + i] = qbase[(size_t)i * HD + e];
        }
    }

    float m_r[4], l_r[4], o_r[4][4];
    #pragma unroll
    for (int u = 0; u < 4; u++) {
        m_r[u] = -1e30f;
        l_r[u] = 0.0f;
        #pragma unroll
        for (int w = 0; w < 4; w++) o_r[u][w] = 0.0f;
    }

    const int nTiles = (S + 63) >> 6;
    for (int ts = 0; ts < nTiles; ts++) {
        const int s0 = ts * 64;
        __syncthreads();

        const float* kbase = k + (size_t)s0 * HD + h * D_KEYS;
        const float* vbase = v + (size_t)s0 * HD + h * D_KEYS;
        #pragma unroll
        for (int t = 0; t < 16; t++) {
            const int idx = t * 256 + tid;
            const int j = idx >> 6;
            const int e = idx & 63;
            const bool valid = (s0 + j) < S;
            KPs[e * AT_PAD + j] = valid ? kbase[(size_t)j * HD + e] : 0.0f;
            Vs[j * AT_PAD + e]  = valid ? vbase[(size_t)j * HD + e] : 0.0f;
        }
        __syncthreads();

        float sv[4][4];
        #pragma unroll
        for (int u = 0; u < 4; u++)
            #pragma unroll
            for (int w = 0; w < 4; w++) sv[u][w] = 0.0f;

        #pragma unroll 8
        for (int e = 0; e < 64; e++) {
            float qa[4], kb[4];
            #pragma unroll
            for (int u = 0; u < 4; u++) qa[u] = Qs[e * AT_PAD + 4 * tr + u];
            #pragma unroll
            for (int w = 0; w < 4; w++) kb[w] = KPs[e * AT_PAD + 4 * tc + w];
            #pragma unroll
            for (int u = 0; u < 4; u++)
                #pragma unroll
                for (int w = 0; w < 4; w++)
                    sv[u][w] = fmaf(qa[u], kb[w], sv[u][w]);
        }

        #pragma unroll
        for (int w = 0; w < 4; w++) {
            const bool valid = (s0 + 4 * tc + w) < S;
            #pragma unroll
            for (int u = 0; u < 4; u++)
                sv[u][w] = valid ? sv[u][w] * scale : -1e30f;
        }

        #pragma unroll
        for (int u = 0; u < 4; u++) {
            float mt = sv[u][0];
            mt = fmaxf(mt, sv[u][1]);
            mt = fmaxf(mt, sv[u][2]);
            mt = fmaxf(mt, sv[u][3]);
            #pragma unroll
            for (int off = 8; off >= 1; off >>= 1)
                mt = fmaxf(mt, __shfl_xor_sync(0xffffffffu, mt, off));
            const float m_new = fmaxf(m_r[u], mt);
            const float fac = __expf(m_r[u] - m_new);
            m_r[u] = m_new;
            l_r[u] *= fac;
            #pragma unroll
            for (int w = 0; w < 4; w++) o_r[u][w] *= fac;

            float rs = 0.0f;
            #pragma unroll
            for (int w = 0; w < 4; w++) {
                const float p = __expf(sv[u][w] - m_new);
                sv[u][w] = p;
                rs += p;
            }
            #pragma unroll
            for (int off = 8; off >= 1; off >>= 1)
                rs += __shfl_xor_sync(0xffffffffu, rs, off);
            l_r[u] += rs;
        }

        __syncthreads();

        #pragma unroll
        for (int w = 0; w < 4; w++)
            #pragma unroll
            for (int u = 0; u < 4; u++)
                KPs[(4 * tc + w) * AT_PAD + 4 * tr + u] = sv[u][w];
        __syncthreads();

        #pragma unroll 8
        for (int s = 0; s < 64; s++) {
            float pa[4], vb[4];
            #pragma unroll
            for (int u = 0; u < 4; u++) pa[u] = KPs[s * AT_PAD + 4 * tr + u];
            #pragma unroll
            for (int w = 0; w < 4; w++) vb[w] = Vs[s * AT_PAD + 4 * tc + w];
            #pragma unroll
            for (int u = 0; u < 4; u++)
                #pragma unroll
                for (int w = 0; w < 4; w++)
                    o_r[u][w] = fmaf(pa[u], vb[w], o_r[u][w]);
        }
    }

    float* obase = o_out + ((size_t)(b * L_DIM + l0)) * HD + h * D_KEYS;
    #pragma unroll
    for (int u = 0; u < 4; u++) {
        const float inv = 1.0f / l_r[u];
        #pragma unroll
        for (int w = 0; w < 4; w++)
            obase[(size_t)(4 * tr + u) * HD + 4 * tc + w] = o_r[u][w] * inv;
    }
}

// ---------------------------------------------------------------------------
// Launch
// ---------------------------------------------------------------------------
extern "C" void kernel_launch(void* const* d_in, const int* in_sizes, int n_in,
                              void* d_out, int out_size)
{
    const float* target = (const float*)d_in[0];
    const float* source = (const float*)d_in[1];
    const float* value  = (const float*)d_in[2];
    const float* Wq = (const float*)d_in[3];
    const float* bq = (const float*)d_in[4];
    const float* Wk = (const float*)d_in[5];
    const float* bk = (const float*)d_in[6];
    const float* Wv = (const float*)d_in[7];
    const float* bv = (const float*)d_in[8];
    const float* Wo = (const float*)d_in[9];
    const float* bo = (const float*)d_in[10];
    const float* alpha = (const float*)d_in[11];
    const float* beta  = (const float*)d_in[12];
    float* out = (float*)d_out;

    const int S = in_sizes[1] / D_LLM;   // 1000

    float *qb, *kb, *vb, *ab;
    cudaGetSymbolAddress((void**)&qb, g_q);
    cudaGetSymbolAddress((void**)&kb, g_k);
    cudaGetSymbolAddress((void**)&vb, g_v);
    cudaGetSymbolAddress((void**)&ab, g_attn);

    dim3 blk(256);

    // Q = target @ Wq + bq          [8192,1024] x [1024,1024]
    gemm_tf32_kernel<<<dim3(HD / BNT, ML / BMT), blk>>>(target, Wq, bq, qb, ML, HD, D_MODEL);
    // K = source @ Wk + bk          [S,4096] x [4096,1024]
    gemm_tf32_kernel<<<dim3(HD / BNT, (S + BMT - 1) / BMT), blk>>>(source, Wk, bk, kb, S, HD, D_LLM);
    // V = value @ Wv + bv
    gemm_tf32_kernel<<<dim3(HD / BNT, (S + BMT - 1) / BMT), blk>>>(value, Wv, bv, vb, S, HD, D_LLM);

    // fused attention
    const size_t smem = 3 * 64 * AT_PAD * sizeof(float);   // ~49.9 KB
    cudaFuncSetAttribute(attn_kernel, cudaFuncAttributeMaxDynamicSharedMemorySize, (int)smem);
    attn_kernel<<<dim3(L_DIM / 64, B_DIM * N_HEADS), blk, smem>>>(qb, kb, vb, ab, alpha, beta, S);

    // out = attn @ Wo + bo          [8192,1024] x [1024,4096]
    gemm_tf32_kernel<<<dim3(D_LLM / BNT, ML / BMT), blk>>>(ab, Wo, bo, out, ML, D_LLM, D_MODEL);
}

// round 3
// speedup vs baseline: 3.3351x; 1.8496x over previous
#include <cuda_runtime.h>
#include <cstdint>

// ---------------------------------------------------------------------------
// Problem constants
// ---------------------------------------------------------------------------
#define B_DIM 8
#define L_DIM 1024
#define D_MODEL 1024
#define N_HEADS 16
#define D_KEYS 64
#define D_LLM 4096
#define HD 1024           // N_HEADS * D_KEYS
#define ML (B_DIM * L_DIM) // 8192 rows of q / attn output

// Scratch (device globals: allocation-free contract)
__device__ float g_q[ML * HD];        // 32 MB
__device__ float g_k[1024 * HD];      // 4 MB (S<=1024)
__device__ float g_v[1024 * HD];      // 4 MB
__device__ float g_attn[ML * HD];     // 32 MB

__device__ __forceinline__ uint32_t f32_to_tf32(float x) {
    uint32_t r;
    asm("cvt.rna.tf32.f32 %0, %1;" : "=r"(r) : "f"(x));
    return r;
}

#define MMA_TF32(d, a, b0v, b1v)                                               \
    asm volatile(                                                              \
        "mma.sync.aligned.m16n8k8.row.col.f32.tf32.tf32.f32 "                  \
        "{%0,%1,%2,%3}, {%4,%5,%6,%7}, {%8,%9}, {%0,%1,%2,%3};"                \
        : "+f"((d)[0]), "+f"((d)[1]), "+f"((d)[2]), "+f"((d)[3])               \
        : "r"((a)[0]), "r"((a)[1]), "r"((a)[2]), "r"((a)[3]),                  \
          "r"(b0v), "r"(b1v))

// ---------------------------------------------------------------------------
// TF32 tensor-core GEMM: C[M,N] = A[M,K] @ W[K,N] + bias[N]
// 128x128 CTA tile, BK=8, 256 threads (8 warps, 2x4), warp tile 64x32.
// ---------------------------------------------------------------------------
#define BMT 128
#define BNT 128
#define BKT 8
#define APITCH 12
#define BPITCH 136

__device__ __forceinline__
void gemm_body(const float* __restrict__ A, const float* __restrict__ W,
               const float* __restrict__ bias, float* __restrict__ C,
               int M, int N, int K)
{
    __shared__ uint32_t As[2][BMT][APITCH];
    __shared__ uint32_t Bs[2][BKT][BPITCH];

    const int tid  = threadIdx.x;
    const int lane = tid & 31;
    const int warp = tid >> 5;
    const int wm = (warp >> 2) * 64;
    const int wn = (warp & 3) * 32;
    const int grp = lane >> 2;
    const int tig = lane & 3;

    const int m0 = blockIdx.y * BMT;
    const int n0 = blockIdx.x * BNT;

    const int la_row = tid >> 1;
    const int la_k   = (tid & 1) << 2;
    const int lb_k   = tid >> 5;
    const int lb_n   = (tid & 31) << 2;

    float acc[4][4][4];
    #pragma unroll
    for (int i = 0; i < 4; i++)
        #pragma unroll
        for (int j = 0; j < 4; j++)
            #pragma unroll
            for (int r = 0; r < 4; r++) acc[i][j][r] = 0.0f;

    const int nk = K / BKT;

    float4 aR, bR;
    {
        const int row = m0 + la_row;
        aR = (row < M) ? *(const float4*)(A + (size_t)row * K + la_k)
                       : make_float4(0.f, 0.f, 0.f, 0.f);
        bR = *(const float4*)(W + (size_t)lb_k * N + n0 + lb_n);
    }
    As[0][la_row][la_k + 0] = f32_to_tf32(aR.x);
    As[0][la_row][la_k + 1] = f32_to_tf32(aR.y);
    As[0][la_row][la_k + 2] = f32_to_tf32(aR.z);
    As[0][la_row][la_k + 3] = f32_to_tf32(aR.w);
    Bs[0][lb_k][lb_n + 0] = f32_to_tf32(bR.x);
    Bs[0][lb_k][lb_n + 1] = f32_to_tf32(bR.y);
    Bs[0][lb_k][lb_n + 2] = f32_to_tf32(bR.z);
    Bs[0][lb_k][lb_n + 3] = f32_to_tf32(bR.w);
    __syncthreads();

    for (int kt = 0; kt < nk; kt++) {
        const int cur = kt & 1;
        if (kt + 1 < nk) {
            const int k0 = (kt + 1) * BKT;
            const int row = m0 + la_row;
            aR = (row < M) ? *(const float4*)(A + (size_t)row * K + k0 + la_k)
                           : make_float4(0.f, 0.f, 0.f, 0.f);
            bR = *(const float4*)(W + (size_t)(k0 + lb_k) * N + n0 + lb_n);
        }

        uint32_t af[4][4], bf[4][2];
        #pragma unroll
        for (int tm = 0; tm < 4; tm++) {
            const int rb = wm + tm * 16 + grp;
            af[tm][0] = As[cur][rb][tig];
            af[tm][1] = As[cur][rb + 8][tig];
            af[tm][2] = As[cur][rb][tig + 4];
            af[tm][3] = As[cur][rb + 8][tig + 4];
        }
        #pragma unroll
        for (int tn = 0; tn < 4; tn++) {
            const int nb = wn + tn * 8 + grp;
            bf[tn][0] = Bs[cur][tig][nb];
            bf[tn][1] = Bs[cur][tig + 4][nb];
        }

        #pragma unroll
        for (int tm = 0; tm < 4; tm++)
            #pragma unroll
            for (int tn = 0; tn < 4; tn++)
                MMA_TF32(acc[tm][tn], af[tm], bf[tn][0], bf[tn][1]);

        if (kt + 1 < nk) {
            const int nxt = cur ^ 1;
            As[nxt][la_row][la_k + 0] = f32_to_tf32(aR.x);
            As[nxt][la_row][la_k + 1] = f32_to_tf32(aR.y);
            As[nxt][la_row][la_k + 2] = f32_to_tf32(aR.z);
            As[nxt][la_row][la_k + 3] = f32_to_tf32(aR.w);
            Bs[nxt][lb_k][lb_n + 0] = f32_to_tf32(bR.x);
            Bs[nxt][lb_k][lb_n + 1] = f32_to_tf32(bR.y);
            Bs[nxt][lb_k][lb_n + 2] = f32_to_tf32(bR.z);
            Bs[nxt][lb_k][lb_n + 3] = f32_to_tf32(bR.w);
            __syncthreads();
        }
    }

    #pragma unroll
    for (int tm = 0; tm < 4; tm++) {
        const int row  = m0 + wm + tm * 16 + grp;
        const int row2 = row + 8;
        #pragma unroll
        for (int tn = 0; tn < 4; tn++) {
            const int col = n0 + wn + tn * 8 + 2 * tig;
            const float b0v = bias[col];
            const float b1v = bias[col + 1];
            if (row < M) {
                float2 o = make_float2(acc[tm][tn][0] + b0v, acc[tm][tn][1] + b1v);
                *(float2*)(C + (size_t)row * N + col) = o;
            }
            if (row2 < M) {
                float2 o = make_float2(acc[tm][tn][2] + b0v, acc[tm][tn][3] + b1v);
                *(float2*)(C + (size_t)row2 * N + col) = o;
            }
        }
    }
}

__global__ __launch_bounds__(256, 2)
void gemm_tf32_kernel(const float* __restrict__ A, const float* __restrict__ W,
                      const float* __restrict__ bias, float* __restrict__ C,
                      int M, int N, int K)
{
    gemm_body(A, W, bias, C, M, N, K);
}

// K and V projections fused: blockIdx.z selects the operand set (2x CTAs in flight)
__global__ __launch_bounds__(256, 2)
void gemm_tf32_dual_kernel(const float* __restrict__ A0, const float* __restrict__ W0,
                           const float* __restrict__ b0, float* __restrict__ C0,
                           const float* __restrict__ A1, const float* __restrict__ W1,
                           const float* __restrict__ b1, float* __restrict__ C1,
                           int M, int N, int K)
{
    if (blockIdx.z == 0) gemm_body(A0, W0, b0, C0, M, N, K);
    else                 gemm_body(A1, W1, b1, C1, M, N, K);
}

// ---------------------------------------------------------------------------
// Tensor-core flash attention (tf32 m16n8k8), head_dim = 64.
// One block per (b, h, 64-query tile). 128 threads = 4 warps.
// Warp w owns query rows [16w, 16w+16). Q fragments live in registers for the
// whole S loop. K/V staged in smem (tf32) with bank-distinct pitches.
// P goes through a per-warp smem region to re-shape accumulator -> A fragment.
// ---------------------------------------------------------------------------
#define QK_PITCH 68   // banks (grp, tig) -> 4*grp + tig : all 32 distinct
#define V_PITCH  72   // banks (tig, grp) -> 8*tig + grp : all 32 distinct
#define P_PITCH  72

__global__ __launch_bounds__(128)
void attn_tc_kernel(const float* __restrict__ q, const float* __restrict__ k,
                    const float* __restrict__ v, float* __restrict__ o_out,
                    const float* __restrict__ alpha, const float* __restrict__ beta,
                    int S)
{
    extern __shared__ uint32_t smu[];
    uint32_t* Qs = smu;                        // 64 x 68
    uint32_t* Ks = Qs + 64 * QK_PITCH;         // 64 x 68
    uint32_t* Vs = Ks + 64 * QK_PITCH;         // 64 x 72
    uint32_t* Ps = Vs + 64 * V_PITCH;          // 64 x 72 (16 rows per warp)

    const int tid  = threadIdx.x;
    const int lane = tid & 31;
    const int warp = tid >> 5;          // 0..3
    const int grp  = lane >> 2;         // 0..7
    const int tig  = lane & 3;          // 0..3

    const int l0 = blockIdx.x * 64;
    const int b  = blockIdx.y >> 4;
    const int h  = blockIdx.y & 15;

    const float scale = alpha[0] * beta[0] * 0.125f;   // 1/sqrt(64)

    // ---- load Q tile -> smem (tf32), coalesced ----
    const float* qbase = q + ((size_t)(b * L_DIM + l0)) * HD + h * D_KEYS;
    #pragma unroll
    for (int p = 0; p < 8; p++) {
        const int idx = p * 128 + tid;      // 1024 float4
        const int row = idx >> 4;
        const int e4  = (idx & 15) << 2;
        float4 t = *(const float4*)(qbase + (size_t)row * HD + e4);
        uint32_t* d = Qs + row * QK_PITCH + e4;
        d[0] = f32_to_tf32(t.x); d[1] = f32_to_tf32(t.y);
        d[2] = f32_to_tf32(t.z); d[3] = f32_to_tf32(t.w);
    }
    __syncthreads();

    // ---- Q fragments in registers (reused for all S tiles) ----
    uint32_t qf[8][4];
    {
        const int qrow = warp * 16 + grp;
        #pragma unroll
        for (int ks = 0; ks < 8; ks++) {
            qf[ks][0] = Qs[qrow * QK_PITCH + ks * 8 + tig];
            qf[ks][1] = Qs[(qrow + 8) * QK_PITCH + ks * 8 + tig];
            qf[ks][2] = Qs[qrow * QK_PITCH + ks * 8 + tig + 4];
            qf[ks][3] = Qs[(qrow + 8) * QK_PITCH + ks * 8 + tig + 4];
        }
    }

    float m0r = -1e30f, m1r = -1e30f, l0r = 0.0f, l1r = 0.0f;
    float oa[8][4];
    #pragma unroll
    for (int nt = 0; nt < 8; nt++)
        #pragma unroll
        for (int r = 0; r < 4; r++) oa[nt][r] = 0.0f;

    const int nTiles = (S + 63) >> 6;
    for (int ts = 0; ts < nTiles; ts++) {
        const int s0 = ts * 64;
        __syncthreads();   // all warps done reading K/V from previous tile

        // ---- load K, V tiles -> smem (tf32), zero-padded ----
        const float* kb2 = k + (size_t)s0 * HD + h * D_KEYS;
        const float* vb2 = v + (size_t)s0 * HD + h * D_KEYS;
        #pragma unroll
        for (int p = 0; p < 8; p++) {
            const int idx = p * 128 + tid;
            const int j  = idx >> 4;
            const int e4 = (idx & 15) << 2;
            float4 tk, tv;
            if (s0 + j < S) {
                tk = *(const float4*)(kb2 + (size_t)j * HD + e4);
                tv = *(const float4*)(vb2 + (size_t)j * HD + e4);
            } else {
                tk = make_float4(0.f, 0.f, 0.f, 0.f);
                tv = tk;
            }
            uint32_t* dk = Ks + j * QK_PITCH + e4;
            dk[0] = f32_to_tf32(tk.x); dk[1] = f32_to_tf32(tk.y);
            dk[2] = f32_to_tf32(tk.z); dk[3] = f32_to_tf32(tk.w);
            uint32_t* dv = Vs + j * V_PITCH + e4;
            dv[0] = f32_to_tf32(tv.x); dv[1] = f32_to_tf32(tv.y);
            dv[2] = f32_to_tf32(tv.z); dv[3] = f32_to_tf32(tv.w);
        }
        __syncthreads();

        // ---- scores: 64 MMAs per warp ----
        float sc[8][4];
        #pragma unroll
        for (int nt = 0; nt < 8; nt++)
            #pragma unroll
            for (int r = 0; r < 4; r++) sc[nt][r] = 0.0f;

        #pragma unroll
        for (int ks = 0; ks < 8; ks++) {
            #pragma unroll
            for (int nt = 0; nt < 8; nt++) {
                const uint32_t b0v = Ks[(nt * 8 + grp) * QK_PITCH + ks * 8 + tig];
                const uint32_t b1v = Ks[(nt * 8 + grp) * QK_PITCH + ks * 8 + tig + 4];
                MMA_TF32(sc[nt], qf[ks], b0v, b1v);
            }
        }

        // ---- scale + mask ----
        #pragma unroll
        for (int nt = 0; nt < 8; nt++) {
            const int c0 = s0 + nt * 8 + 2 * tig;
            const bool v0 = c0 < S, v1 = (c0 + 1) < S;
            sc[nt][0] = v0 ? sc[nt][0] * scale : -1e30f;
            sc[nt][1] = v1 ? sc[nt][1] * scale : -1e30f;
            sc[nt][2] = v0 ? sc[nt][2] * scale : -1e30f;
            sc[nt][3] = v1 ? sc[nt][3] * scale : -1e30f;
        }

        // ---- online softmax (rows r0 = grp, r1 = grp+8 of warp tile) ----
        float mt0 = -1e30f, mt1 = -1e30f;
        #pragma unroll
        for (int nt = 0; nt < 8; nt++) {
            mt0 = fmaxf(mt0, fmaxf(sc[nt][0], sc[nt][1]));
            mt1 = fmaxf(mt1, fmaxf(sc[nt][2], sc[nt][3]));
        }
        mt0 = fmaxf(mt0, __shfl_xor_sync(0xffffffffu, mt0, 1));
        mt0 = fmaxf(mt0, __shfl_xor_sync(0xffffffffu, mt0, 2));
        mt1 = fmaxf(mt1, __shfl_xor_sync(0xffffffffu, mt1, 1));
        mt1 = fmaxf(mt1, __shfl_xor_sync(0xffffffffu, mt1, 2));

        const float mn0 = fmaxf(m0r, mt0);
        const float mn1 = fmaxf(m1r, mt1);
        const float fac0 = __expf(m0r - mn0);
        const float fac1 = __expf(m1r - mn1);
        m0r = mn0; m1r = mn1;
        l0r *= fac0; l1r *= fac1;
        #pragma unroll
        for (int nt = 0; nt < 8; nt++) {
            oa[nt][0] *= fac0; oa[nt][1] *= fac0;
            oa[nt][2] *= fac1; oa[nt][3] *= fac1;
        }

        float rs0 = 0.0f, rs1 = 0.0f;
        #pragma unroll
        for (int nt = 0; nt < 8; nt++) {
            sc[nt][0] = __expf(sc[nt][0] - mn0);
            sc[nt][1] = __expf(sc[nt][1] - mn0);
            sc[nt][2] = __expf(sc[nt][2] - mn1);
            sc[nt][3] = __expf(sc[nt][3] - mn1);
            rs0 += sc[nt][0] + sc[nt][1];
            rs1 += sc[nt][2] + sc[nt][3];
        }
        rs0 += __shfl_xor_sync(0xffffffffu, rs0, 1);
        rs0 += __shfl_xor_sync(0xffffffffu, rs0, 2);
        rs1 += __shfl_xor_sync(0xffffffffu, rs1, 1);
        rs1 += __shfl_xor_sync(0xffffffffu, rs1, 2);
        l0r += rs0; l1r += rs1;

        // ---- store P to per-warp smem region (tf32), accumulator layout ----
        {
            const int pr0 = warp * 16 + grp;
            #pragma unroll
            for (int nt = 0; nt < 8; nt++) {
                uint2 p01 = make_uint2(f32_to_tf32(sc[nt][0]), f32_to_tf32(sc[nt][1]));
                uint2 p23 = make_uint2(f32_to_tf32(sc[nt][2]), f32_to_tf32(sc[nt][3]));
                *(uint2*)&Ps[pr0 * P_PITCH + nt * 8 + 2 * tig] = p01;
                *(uint2*)&Ps[(pr0 + 8) * P_PITCH + nt * 8 + 2 * tig] = p23;
            }
        }
        __syncwarp();

        // ---- O += P @ V : 64 MMAs per warp ----
        #pragma unroll
        for (int ks = 0; ks < 8; ks++) {
            uint32_t af[4];
            const int pr0 = warp * 16 + grp;
            af[0] = Ps[pr0 * P_PITCH + ks * 8 + tig];
            af[1] = Ps[(pr0 + 8) * P_PITCH + ks * 8 + tig];
            af[2] = Ps[pr0 * P_PITCH + ks * 8 + tig + 4];
            af[3] = Ps[(pr0 + 8) * P_PITCH + ks * 8 + tig + 4];
            #pragma unroll
            for (int nt = 0; nt < 8; nt++) {
                const uint32_t b0v = Vs[(ks * 8 + tig) * V_PITCH + nt * 8 + grp];
                const uint32_t b1v = Vs[(ks * 8 + tig + 4) * V_PITCH + nt * 8 + grp];
                MMA_TF32(oa[nt], af, b0v, b1v);
            }
        }
    }

    // ---- normalize + store ----
    const float inv0 = 1.0f / l0r;
    const float inv1 = 1.0f / l1r;
    float* ob = o_out + ((size_t)(b * L_DIM + l0 + warp * 16 + grp)) * HD + h * D_KEYS;
    #pragma unroll
    for (int nt = 0; nt < 8; nt++) {
        const int col = nt * 8 + 2 * tig;
        *(float2*)(ob + col) = make_float2(oa[nt][0] * inv0, oa[nt][1] * inv0);
        *(float2*)(ob + (size_t)8 * HD + col) = make_float2(oa[nt][2] * inv1, oa[nt][3] * inv1);
    }
}

// ---------------------------------------------------------------------------
// Launch
// ---------------------------------------------------------------------------
extern "C" void kernel_launch(void* const* d_in, const int* in_sizes, int n_in,
                              void* d_out, int out_size)
{
    const float* target = (const float*)d_in[0];
    const float* source = (const float*)d_in[1];
    const float* value  = (const float*)d_in[2];
    const float* Wq = (const float*)d_in[3];
    const float* bq = (const float*)d_in[4];
    const float* Wk = (const float*)d_in[5];
    const float* bk = (const float*)d_in[6];
    const float* Wv = (const float*)d_in[7];
    const float* bv = (const float*)d_in[8];
    const float* Wo = (const float*)d_in[9];
    const float* bo = (const float*)d_in[10];
    const float* alpha = (const float*)d_in[11];
    const float* beta  = (const float*)d_in[12];
    float* out = (float*)d_out;

    const int S = in_sizes[1] / D_LLM;   // 1000

    float *qb, *kb, *vb, *ab;
    cudaGetSymbolAddress((void**)&qb, g_q);
    cudaGetSymbolAddress((void**)&kb, g_k);
    cudaGetSymbolAddress((void**)&vb, g_v);
    cudaGetSymbolAddress((void**)&ab, g_attn);

    dim3 blk(256);

    // Q = target @ Wq + bq          [8192,1024] x [1024,1024]
    gemm_tf32_kernel<<<dim3(HD / BNT, ML / BMT), blk>>>(target, Wq, bq, qb, ML, HD, D_MODEL);
    // K,V projections fused (2x CTA parallelism)
    gemm_tf32_dual_kernel<<<dim3(HD / BNT, (S + BMT - 1) / BMT, 2), blk>>>(
        source, Wk, bk, kb, value, Wv, bv, vb, S, HD, D_LLM);

    // fused tensor-core attention
    const size_t smem = (2 * 64 * QK_PITCH + 2 * 64 * V_PITCH) * sizeof(uint32_t); // ~71.7 KB
    cudaFuncSetAttribute(attn_tc_kernel, cudaFuncAttributeMaxDynamicSharedMemorySize, (int)smem);
    attn_tc_kernel<<<dim3(L_DIM / 64, B_DIM * N_HEADS), dim3(128), smem>>>(
        qb, kb, vb, ab, alpha, beta, S);

    // out = attn @ Wo + bo          [8192,1024] x [1024,4096]
    gemm_tf32_kernel<<<dim3(D_LLM / BNT, ML / BMT), blk>>>(ab, Wo, bo, out, ML, D_LLM, D_MODEL);
}